// round 9
// baseline (speedup 1.0000x reference)
#include <cuda_runtime.h>
#include <cuda_fp16.h>
#include <cstdint>
#include <cstddef>

// Problem constants
#define NMAX 10000
#define EMAX 160000
#define DIN 32
#define DOUT 64
#define DHID 128
#define BFD 13
#define KDIM (DHID * DIN)      // 4096
#define KTOT (KDIM + 2 * DIN)  // 4160 = S | Sx | x
#define NTILES (KTOT / 32)     // 130 k-tiles of 32 halfs

// ---------------- scratch (device globals; no allocations allowed) ------------
__device__ int    g_deg[NMAX];
__device__ int    g_rowptr[NMAX + 1];
__device__ int    g_cursor[NMAX];
__device__ int    g_src[EMAX];
__device__ int    g_dst[EMAX];
__device__ int    g_pos[EMAX];           // edge -> CSR slot
__device__ int    g_csr_src[EMAX];
__device__ __half g_h[(size_t)EMAX * DHID];     // 41 MB, CSR order
__device__ __half g_S[(size_t)NMAX * KDIM];     // 82 MB
__device__ __half g_Sx[(size_t)NMAX * DIN];
__device__ __half g_xh[(size_t)NMAX * DIN];
__device__ __half g_Wt[(size_t)DOUT * KTOT];    // B^T: [64][4160]

// ---------------- small PTX helpers -------------------------------------------
__device__ __forceinline__ uint32_t smem_to_u32(const void* p) {
    uint32_t a;
    asm("{ .reg .u64 t; cvta.to.shared.u64 t, %1; cvt.u32.u64 %0, t; }" : "=r"(a) : "l"(p));
    return a;
}
__device__ __forceinline__ void cp16(uint32_t saddr, const void* g) {
    asm volatile("cp.async.cg.shared.global [%0], [%1], 16;" :: "r"(saddr), "l"(g));
}
#define CP_COMMIT() asm volatile("cp.async.commit_group;" ::: "memory")

__device__ __forceinline__ void mma_f16(float* d, const uint32_t* a, const uint32_t* b) {
    asm volatile("mma.sync.aligned.m16n8k16.row.col.f32.f16.f16.f32 "
        "{%0,%1,%2,%3}, {%4,%5,%6,%7}, {%8,%9}, {%0,%1,%2,%3};"
        : "+f"(d[0]), "+f"(d[1]), "+f"(d[2]), "+f"(d[3])
        : "r"(a[0]), "r"(a[1]), "r"(a[2]), "r"(a[3]), "r"(b[0]), "r"(b[1]));
}

// ---------------- decode + degree count (detect int64 inline) -----------------
__global__ void decode_count_kernel(const void* ei, int E) {
    __shared__ int s64;
    if (threadIdx.x == 0) {
        const int* w = (const int*)ei;
        long long s = 0;
        #pragma unroll 8
        for (int i = 0; i < 64; i++) s += w[2 * i + 1];
        s64 = (s == 0) ? 1 : 0;
    }
    __syncthreads();
    bool is64 = (s64 != 0);
    int i = blockIdx.x * blockDim.x + threadIdx.x;
    int stride = gridDim.x * blockDim.x;
    for (int e = i; e < E; e += stride) {
        int s, d;
        if (is64) {
            const long long* p = (const long long*)ei;
            s = (int)p[e]; d = (int)p[E + e];
        } else {
            const int* p = (const int*)ei;
            s = p[e]; d = p[E + e];
        }
        g_src[e] = s;
        g_dst[e] = d;
        atomicAdd(&g_deg[d], 1);
    }
}

// ---------------- single-block exclusive scan over degrees --------------------
__global__ __launch_bounds__(1024) void scan_kernel(int n) {
    __shared__ int wsum[32];
    __shared__ int carry_s;
    int tid = threadIdx.x, lane = tid & 31, wid = tid >> 5;
    if (tid == 0) carry_s = 0;
    __syncthreads();
    for (int base = 0; base < n; base += 1024) {
        int i = base + tid;
        int v = (i < n) ? g_deg[i] : 0;
        int incl = v;
        #pragma unroll
        for (int d = 1; d < 32; d <<= 1) {
            int y = __shfl_up_sync(0xffffffffu, incl, d);
            if (lane >= d) incl += y;
        }
        if (lane == 31) wsum[wid] = incl;
        __syncthreads();
        if (wid == 0) {
            int s = wsum[lane];
            #pragma unroll
            for (int d = 1; d < 32; d <<= 1) {
                int y = __shfl_up_sync(0xffffffffu, s, d);
                if (lane >= d) s += y;
            }
            wsum[lane] = s;
        }
        __syncthreads();
        int excl = incl - v + ((wid > 0) ? wsum[wid - 1] : 0) + carry_s;
        if (i < n) { g_rowptr[i] = excl; g_cursor[i] = excl; }
        int total = wsum[31];
        __syncthreads();
        if (tid == 0) carry_s += total;
        __syncthreads();
    }
    if (tid == 0) g_rowptr[n] = carry_s;
}

// ---------------- scatter edges into dst-CSR ----------------------------------
__global__ void scatter_kernel(int E) {
    int i = blockIdx.x * blockDim.x + threadIdx.x;
    int stride = gridDim.x * blockDim.x;
    for (int e = i; e < E; e += stride) {
        int d = g_dst[e];
        int pos = atomicAdd(&g_cursor[d], 1);
        g_csr_src[pos] = g_src[e];
        g_pos[e] = pos;
    }
}

// ---------------- h = relu(edge_attr @ W1 + b1), written in CSR order ---------
__global__ __launch_bounds__(128) void h_kernel(const float* __restrict__ attr,
                                                const float* __restrict__ W1,
                                                const float* __restrict__ b1, int E) {
    __shared__ float w1s[BFD * DHID];
    __shared__ float b1s[DHID];
    for (int i = threadIdx.x; i < BFD * DHID; i += blockDim.x) w1s[i] = W1[i];
    if (threadIdx.x < DHID) b1s[threadIdx.x] = b1[threadIdx.x];
    __syncthreads();
    int warp = (blockIdx.x * blockDim.x + threadIdx.x) >> 5;
    int lane = threadIdx.x & 31;
    int nwarps = (gridDim.x * blockDim.x) >> 5;
    for (int e = warp; e < E; e += nwarps) {
        float a0 = b1s[lane], a1 = b1s[lane + 32], a2 = b1s[lane + 64], a3 = b1s[lane + 96];
        const float* ea = attr + (size_t)e * BFD;
        #pragma unroll
        for (int f = 0; f < BFD; f++) {
            float av = __ldg(&ea[f]);
            a0 += av * w1s[f * DHID + lane];
            a1 += av * w1s[f * DHID + lane + 32];
            a2 += av * w1s[f * DHID + lane + 64];
            a3 += av * w1s[f * DHID + lane + 96];
        }
        __half* hp = g_h + (size_t)g_pos[e] * DHID;
        hp[lane]      = __float2half_rn(fmaxf(a0, 0.f));
        hp[lane + 32] = __float2half_rn(fmaxf(a1, 0.f));
        hp[lane + 64] = __float2half_rn(fmaxf(a2, 0.f));
        hp[lane + 96] = __float2half_rn(fmaxf(a3, 0.f));
    }
}

// ---------------- build g_Wt[o][k] = B[k][o] (half), B = [W2 | b2 | root] -----
__global__ __launch_bounds__(1024) void wt_kernel(const float* __restrict__ W2,
                                                  const float* __restrict__ b2,
                                                  const float* __restrict__ root) {
    __shared__ float tile[32][33];
    int k0 = blockIdx.x * 32, n0 = blockIdx.y * 32;
    int tx = threadIdx.x, ty = threadIdx.y;
    int k = k0 + ty, n = n0 + tx;
    float v;
    if (k < KDIM)            v = W2[(size_t)k * DOUT + n];
    else if (k < KDIM + DIN) v = b2[(size_t)(k - KDIM) * DOUT + n];
    else                     v = root[(size_t)(k - KDIM - DIN) * DOUT + n];
    tile[ty][tx] = v;
    __syncthreads();
    g_Wt[(size_t)(n0 + ty) * KTOT + k0 + tx] = __float2half_rn(tile[tx][ty]);
}

// ---------------- x -> half ----------------------------------------------------
__global__ void xh_kernel(const float* __restrict__ x, int total) {
    int i = blockIdx.x * blockDim.x + threadIdx.x;
    if (i < total) g_xh[i] = __float2half_rn(x[i]);
}

// ---------------- S[n,k,i] = sum_{e->n} h_e[k] * x_src[i];  Sx[n,i] -----------
__global__ __launch_bounds__(128) void sbuild_kernel(const float* __restrict__ x, int n_nodes) {
    int n = blockIdx.x;
    if (n >= n_nodes) return;
    int t = threadIdx.x;   // 0..127 == k
    __shared__ float xs[4][DIN];
    float acc[DIN];
    #pragma unroll
    for (int i = 0; i < DIN; i++) acc[i] = 0.f;
    float sxa = 0.f;
    int beg = g_rowptr[n], end = g_rowptr[n + 1];
    int idx = beg;
    for (; idx + 4 <= end; idx += 4) {
        int j = t >> 5, i = t & 31;
        int srcj = g_csr_src[idx + j];
        xs[j][i] = x[(size_t)srcj * DIN + i];
        float hv0 = __half2float(g_h[(size_t)(idx + 0) * DHID + t]);
        float hv1 = __half2float(g_h[(size_t)(idx + 1) * DHID + t]);
        float hv2 = __half2float(g_h[(size_t)(idx + 2) * DHID + t]);
        float hv3 = __half2float(g_h[(size_t)(idx + 3) * DHID + t]);
        __syncthreads();
        #pragma unroll
        for (int c = 0; c < DIN; c++)
            acc[c] += hv0 * xs[0][c] + hv1 * xs[1][c] + hv2 * xs[2][c] + hv3 * xs[3][c];
        if (t < DIN) sxa += xs[0][t] + xs[1][t] + xs[2][t] + xs[3][t];
        __syncthreads();
    }
    for (; idx < end; idx++) {
        if (t < DIN) xs[0][t] = x[(size_t)g_csr_src[idx] * DIN + t];
        float hv = __half2float(g_h[(size_t)idx * DHID + t]);
        __syncthreads();
        #pragma unroll
        for (int c = 0; c < DIN; c++) acc[c] += hv * xs[0][c];
        if (t < DIN) sxa += xs[0][t];
        __syncthreads();
    }
    // store 32 halfs = 16 x half2 via vector stores
    __half2 packed[16];
    #pragma unroll
    for (int q = 0; q < 16; q++)
        packed[q] = __floats2half2_rn(acc[2 * q], acc[2 * q + 1]);
    uint4* Srow = (uint4*)(g_S + (size_t)n * KDIM + t * DIN);
    const uint4* ps = (const uint4*)packed;
    #pragma unroll
    for (int q = 0; q < 4; q++) Srow[q] = ps[q];
    if (t < DIN) g_Sx[(size_t)n * DIN + t] = __float2half_rn(sxa);
}

// ---------------- fp16 mma GEMM: out = relu([S|Sx|x] @ Wt^T + bias) -----------
// Block: 64 M-rows, 64 N-cols, 8 warps in 4x2 grid, each 16(M)x32(N).
// K tiled by 32 halfs, 3-stage cp.async, pitch 40 halfs (80B, conflict-free).
#define MT 64
#define PITCHH 40
#define A_STAGE (MT * PITCHH)           // 2560 halfs
#define B_STAGE (DOUT * PITCHH)         // 2560 halfs
#define STAGE_H (A_STAGE + B_STAGE)
#define NS 3
#define GEMM_SMEM (NS * STAGE_H * 2)

__device__ __forceinline__ void load_tile(int t, uint32_t sAu, uint32_t sBu, int m0, int n_nodes) {
    int tid = threadIdx.x;
    int k0 = t * 32;
    // A: 64 rows x 32 halfs; 4 threads/row, 8 halfs (16B) each
    {
        int r = tid >> 2, c0 = (tid & 3) * 8;
        int m = m0 + r;
        if (m >= n_nodes) m = n_nodes - 1;
        const __half* g;
        if (t < 128)       g = g_S  + (size_t)m * KDIM + k0 + c0;
        else if (t == 128) g = g_Sx + (size_t)m * DIN + c0;
        else               g = g_xh + (size_t)m * DIN + c0;
        cp16(sAu + (r * PITCHH + c0) * 2, g);
    }
    // B: 64 n-rows x 32 halfs
    {
        int nr = tid >> 2, c0 = (tid & 3) * 8;
        cp16(sBu + (nr * PITCHH + c0) * 2, g_Wt + (size_t)nr * KTOT + k0 + c0);
    }
}

__global__ __launch_bounds__(256) void gemm_mma_kernel(const float* __restrict__ bias,
                                                       float* __restrict__ out, int n_nodes) {
    extern __shared__ __half smem[];
    uint32_t smem_u = smem_to_u32(smem);
    int tid = threadIdx.x, wid = tid >> 5, lane = tid & 31;
    int wm = wid >> 1, wn = wid & 1;     // 4 x 2 warp grid
    int gid = lane >> 2, tig = lane & 3;
    int m0 = blockIdx.x * MT;

    float acc[4][4];
    #pragma unroll
    for (int nt = 0; nt < 4; nt++)
        #pragma unroll
        for (int r = 0; r < 4; r++) acc[nt][r] = 0.f;

    #pragma unroll
    for (int t = 0; t < NS - 1; t++) {
        load_tile(t, smem_u + t * STAGE_H * 2, smem_u + (t * STAGE_H + A_STAGE) * 2, m0, n_nodes);
        CP_COMMIT();
    }

    for (int t = 0; t < NTILES; t++) {
        asm volatile("cp.async.wait_group %0;" :: "n"(NS - 2) : "memory");
        __syncthreads();
        int tn = t + NS - 1;
        if (tn < NTILES) {
            int s = tn % NS;
            load_tile(tn, smem_u + s * STAGE_H * 2, smem_u + (s * STAGE_H + A_STAGE) * 2, m0, n_nodes);
        }
        CP_COMMIT();

        const __half* As = smem + (t % NS) * STAGE_H;
        const __half* Bs = As + A_STAGE;
        #pragma unroll
        for (int kc = 0; kc < 2; kc++) {
            int col = kc * 16 + 2 * tig;
            uint32_t a[4];
            {
                int r0 = wm * 16 + gid;
                a[0] = *(const uint32_t*)&As[r0 * PITCHH + col];
                a[1] = *(const uint32_t*)&As[(r0 + 8) * PITCHH + col];
                a[2] = *(const uint32_t*)&As[r0 * PITCHH + col + 8];
                a[3] = *(const uint32_t*)&As[(r0 + 8) * PITCHH + col + 8];
            }
            #pragma unroll
            for (int nt = 0; nt < 4; nt++) {
                int n0 = wn * 32 + nt * 8 + gid;
                uint32_t b[2];
                b[0] = *(const uint32_t*)&Bs[n0 * PITCHH + col];
                b[1] = *(const uint32_t*)&Bs[n0 * PITCHH + col + 8];
                mma_f16(acc[nt], a, b);
            }
        }
        __syncthreads();
    }

    // epilogue: bias + relu, fragment layout m16n8
    #pragma unroll
    for (int nt = 0; nt < 4; nt++) {
        int o = wn * 32 + nt * 8 + tig * 2;
        float b0 = __ldg(&bias[o]), b1 = __ldg(&bias[o + 1]);
        #pragma unroll
        for (int half_ = 0; half_ < 2; half_++) {
            int n = m0 + wm * 16 + gid + half_ * 8;
            if (n < n_nodes) {
                float2 v;
                v.x = fmaxf(acc[nt][2 * half_ + 0] + b0, 0.f);
                v.y = fmaxf(acc[nt][2 * half_ + 1] + b1, 0.f);
                *(float2*)(out + (size_t)n * DOUT + o) = v;
            }
        }
    }
}

// ---------------- launch ------------------------------------------------------
extern "C" void kernel_launch(void* const* d_in, const int* in_sizes, int n_in,
                              void* d_out, int out_size) {
    const float* x    = (const float*)d_in[0];
    const void*  ei   = d_in[1];
    const float* attr = (const float*)d_in[2];
    const float* W1   = (const float*)d_in[3];
    const float* b1   = (const float*)d_in[4];
    const float* W2   = (const float*)d_in[5];
    const float* b2   = (const float*)d_in[6];
    const float* root = (const float*)d_in[7];
    const float* bias = (const float*)d_in[8];
    float* out = (float*)d_out;

    int N = in_sizes[0] / DIN;
    int E = in_sizes[2] / BFD;
    if (N > NMAX) N = NMAX;
    if (E > EMAX) E = EMAX;

    void* degp = nullptr;
    cudaGetSymbolAddress(&degp, g_deg);
    cudaMemsetAsync(degp, 0, (size_t)N * sizeof(int));

    static int smem_set = 0;
    if (!smem_set) {
        cudaFuncSetAttribute(gemm_mma_kernel, cudaFuncAttributeMaxDynamicSharedMemorySize, GEMM_SMEM);
        smem_set = 1;
    }

    decode_count_kernel<<<264, 256>>>(ei, E);
    scan_kernel<<<1, 1024>>>(N);
    scatter_kernel<<<264, 256>>>(E);
    h_kernel<<<896, 128>>>(attr, W1, b1, E);
    wt_kernel<<<dim3(NTILES, 2), dim3(32, 32)>>>(W2, b2, root);
    xh_kernel<<<(N * DIN + 255) / 256, 256>>>(x, N * DIN);
    sbuild_kernel<<<N, 128>>>(x, N);
    gemm_mma_kernel<<<(N + MT - 1) / MT, 256, GEMM_SMEM>>>(bias, out, N);
}

// round 10
// speedup vs baseline: 1.5097x; 1.5097x over previous
#include <cuda_runtime.h>
#include <cuda_fp16.h>
#include <cstdint>
#include <cstddef>

// Problem constants
#define NMAX 10000
#define EMAX 160000
#define DIN 32
#define DOUT 64
#define DHID 128
#define BFD 13
#define KDIM (DHID * DIN)      // 4096
#define KTOT (KDIM + 2 * DIN)  // 4160 = S | Sx | x
#define NTILES (KTOT / 32)     // 130 k-tiles of 32 halfs

// ---------------- scratch (device globals; no allocations allowed) ------------
__device__ int    g_deg[NMAX];
__device__ int    g_rowptr[NMAX + 1];
__device__ int    g_cursor[NMAX];
__device__ int    g_src[EMAX];
__device__ int    g_dst[EMAX];
__device__ int    g_pos[EMAX];           // edge -> CSR slot
__device__ int    g_csr_src[EMAX];
__device__ __half g_h[(size_t)EMAX * DHID];     // 41 MB, CSR order
__device__ __half g_S[(size_t)NMAX * KDIM];     // 82 MB
__device__ __half g_Sx[(size_t)NMAX * DIN];
__device__ __half g_xh[(size_t)NMAX * DIN];
__device__ __half g_Wt[(size_t)DOUT * KTOT];    // B^T: [64][4160]

// ---------------- small PTX helpers -------------------------------------------
__device__ __forceinline__ uint32_t smem_to_u32(const void* p) {
    uint32_t a;
    asm("{ .reg .u64 t; cvta.to.shared.u64 t, %1; cvt.u32.u64 %0, t; }" : "=r"(a) : "l"(p));
    return a;
}
__device__ __forceinline__ void cp16(uint32_t saddr, const void* g) {
    asm volatile("cp.async.cg.shared.global [%0], [%1], 16;" :: "r"(saddr), "l"(g));
}
#define CP_COMMIT() asm volatile("cp.async.commit_group;" ::: "memory")

__device__ __forceinline__ void mma_f16(float* d, const uint32_t* a, const uint32_t* b) {
    asm volatile("mma.sync.aligned.m16n8k16.row.col.f32.f16.f16.f32 "
        "{%0,%1,%2,%3}, {%4,%5,%6,%7}, {%8,%9}, {%0,%1,%2,%3};"
        : "+f"(d[0]), "+f"(d[1]), "+f"(d[2]), "+f"(d[3])
        : "r"(a[0]), "r"(a[1]), "r"(a[2]), "r"(a[3]), "r"(b[0]), "r"(b[1]));
}

// ---------------- decode + degree count (detect int64 inline) -----------------
__global__ void decode_count_kernel(const void* ei, int E) {
    __shared__ int s64;
    if (threadIdx.x == 0) {
        const int* w = (const int*)ei;
        long long s = 0;
        #pragma unroll 8
        for (int i = 0; i < 64; i++) s += w[2 * i + 1];
        s64 = (s == 0) ? 1 : 0;
    }
    __syncthreads();
    bool is64 = (s64 != 0);
    int i = blockIdx.x * blockDim.x + threadIdx.x;
    int stride = gridDim.x * blockDim.x;
    for (int e = i; e < E; e += stride) {
        int s, d;
        if (is64) {
            const long long* p = (const long long*)ei;
            s = (int)p[e]; d = (int)p[E + e];
        } else {
            const int* p = (const int*)ei;
            s = p[e]; d = p[E + e];
        }
        g_src[e] = s;
        g_dst[e] = d;
        atomicAdd(&g_deg[d], 1);
    }
}

// ---------------- single-block exclusive scan over degrees --------------------
__global__ __launch_bounds__(1024) void scan_kernel(int n) {
    __shared__ int wsum[32];
    __shared__ int carry_s;
    int tid = threadIdx.x, lane = tid & 31, wid = tid >> 5;
    if (tid == 0) carry_s = 0;
    __syncthreads();
    for (int base = 0; base < n; base += 1024) {
        int i = base + tid;
        int v = (i < n) ? g_deg[i] : 0;
        int incl = v;
        #pragma unroll
        for (int d = 1; d < 32; d <<= 1) {
            int y = __shfl_up_sync(0xffffffffu, incl, d);
            if (lane >= d) incl += y;
        }
        if (lane == 31) wsum[wid] = incl;
        __syncthreads();
        if (wid == 0) {
            int s = wsum[lane];
            #pragma unroll
            for (int d = 1; d < 32; d <<= 1) {
                int y = __shfl_up_sync(0xffffffffu, s, d);
                if (lane >= d) s += y;
            }
            wsum[lane] = s;
        }
        __syncthreads();
        int excl = incl - v + ((wid > 0) ? wsum[wid - 1] : 0) + carry_s;
        if (i < n) { g_rowptr[i] = excl; g_cursor[i] = excl; }
        int total = wsum[31];
        __syncthreads();
        if (tid == 0) carry_s += total;
        __syncthreads();
    }
    if (tid == 0) g_rowptr[n] = carry_s;
}

// ---------------- scatter edges into dst-CSR ----------------------------------
__global__ void scatter_kernel(int E) {
    int i = blockIdx.x * blockDim.x + threadIdx.x;
    int stride = gridDim.x * blockDim.x;
    for (int e = i; e < E; e += stride) {
        int d = g_dst[e];
        int pos = atomicAdd(&g_cursor[d], 1);
        g_csr_src[pos] = g_src[e];
        g_pos[e] = pos;
    }
}

// ---------------- h = relu(edge_attr @ W1 + b1), W1 in REGISTERS --------------
// Thread owns cols {2*lane, 2*lane+1, 2*lane+64, 2*lane+65}; warp covers a row.
__global__ __launch_bounds__(256) void h_kernel(const float* __restrict__ attr,
                                                const float* __restrict__ W1,
                                                const float* __restrict__ b1, int E) {
    int lane = threadIdx.x & 31;
    int gwarp = (blockIdx.x * blockDim.x + threadIdx.x) >> 5;
    int nwarps = (gridDim.x * blockDim.x) >> 5;
    int cA = 2 * lane, cB = 2 * lane + 64;
    float w1r[BFD][4];
    #pragma unroll
    for (int f = 0; f < BFD; f++) {
        w1r[f][0] = __ldg(&W1[f * DHID + cA]);
        w1r[f][1] = __ldg(&W1[f * DHID + cA + 1]);
        w1r[f][2] = __ldg(&W1[f * DHID + cB]);
        w1r[f][3] = __ldg(&W1[f * DHID + cB + 1]);
    }
    float b0 = __ldg(&b1[cA]), b1v = __ldg(&b1[cA + 1]);
    float b2v = __ldg(&b1[cB]), b3v = __ldg(&b1[cB + 1]);

    for (int e = gwarp; e < E; e += nwarps) {
        const float* ea = attr + (size_t)e * BFD;
        float av[BFD];
        #pragma unroll
        for (int f = 0; f < BFD; f++) av[f] = __ldg(&ea[f]);
        float a0 = b0, a1 = b1v, a2 = b2v, a3 = b3v;
        #pragma unroll
        for (int f = 0; f < BFD; f++) {
            a0 += av[f] * w1r[f][0];
            a1 += av[f] * w1r[f][1];
            a2 += av[f] * w1r[f][2];
            a3 += av[f] * w1r[f][3];
        }
        __half* hp = g_h + (size_t)g_pos[e] * DHID;
        *(__half2*)(hp + cA) = __floats2half2_rn(fmaxf(a0, 0.f), fmaxf(a1, 0.f));
        *(__half2*)(hp + cB) = __floats2half2_rn(fmaxf(a2, 0.f), fmaxf(a3, 0.f));
    }
}

// ---------------- build g_Wt[o][k] = B[k][o] (half), B = [W2 | b2 | root] -----
__global__ __launch_bounds__(1024) void wt_kernel(const float* __restrict__ W2,
                                                  const float* __restrict__ b2,
                                                  const float* __restrict__ root) {
    __shared__ float tile[32][33];
    int k0 = blockIdx.x * 32, n0 = blockIdx.y * 32;
    int tx = threadIdx.x, ty = threadIdx.y;
    int k = k0 + ty, n = n0 + tx;
    float v;
    if (k < KDIM)            v = W2[(size_t)k * DOUT + n];
    else if (k < KDIM + DIN) v = b2[(size_t)(k - KDIM) * DOUT + n];
    else                     v = root[(size_t)(k - KDIM - DIN) * DOUT + n];
    tile[ty][tx] = v;
    __syncthreads();
    g_Wt[(size_t)(n0 + ty) * KTOT + k0 + tx] = __float2half_rn(tile[tx][ty]);
}

// ---------------- x -> half ----------------------------------------------------
__global__ void xh_kernel(const float* __restrict__ x, int total) {
    int i = blockIdx.x * blockDim.x + threadIdx.x;
    if (i < total) g_xh[i] = __float2half_rn(x[i]);
}

// ---------------- S[n,k,i] = sum_{e->n} h_e[k] * x_src[i];  Sx[n,i] -----------
__global__ __launch_bounds__(128) void sbuild_kernel(const float* __restrict__ x, int n_nodes) {
    int n = blockIdx.x;
    if (n >= n_nodes) return;
    int t = threadIdx.x;   // 0..127 == k
    __shared__ float xs[4][DIN];
    float acc[DIN];
    #pragma unroll
    for (int i = 0; i < DIN; i++) acc[i] = 0.f;
    float sxa = 0.f;
    int beg = g_rowptr[n], end = g_rowptr[n + 1];
    int idx = beg;
    for (; idx + 4 <= end; idx += 4) {
        int j = t >> 5, i = t & 31;
        int srcj = g_csr_src[idx + j];
        xs[j][i] = x[(size_t)srcj * DIN + i];
        float hv0 = __half2float(g_h[(size_t)(idx + 0) * DHID + t]);
        float hv1 = __half2float(g_h[(size_t)(idx + 1) * DHID + t]);
        float hv2 = __half2float(g_h[(size_t)(idx + 2) * DHID + t]);
        float hv3 = __half2float(g_h[(size_t)(idx + 3) * DHID + t]);
        __syncthreads();
        #pragma unroll
        for (int c = 0; c < DIN; c++)
            acc[c] += hv0 * xs[0][c] + hv1 * xs[1][c] + hv2 * xs[2][c] + hv3 * xs[3][c];
        if (t < DIN) sxa += xs[0][t] + xs[1][t] + xs[2][t] + xs[3][t];
        __syncthreads();
    }
    for (; idx < end; idx++) {
        if (t < DIN) xs[0][t] = x[(size_t)g_csr_src[idx] * DIN + t];
        float hv = __half2float(g_h[(size_t)idx * DHID + t]);
        __syncthreads();
        #pragma unroll
        for (int c = 0; c < DIN; c++) acc[c] += hv * xs[0][c];
        if (t < DIN) sxa += xs[0][t];
        __syncthreads();
    }
    // store 32 halfs = 16 x half2 via vector stores
    __half2 packed[16];
    #pragma unroll
    for (int q = 0; q < 16; q++)
        packed[q] = __floats2half2_rn(acc[2 * q], acc[2 * q + 1]);
    uint4* Srow = (uint4*)(g_S + (size_t)n * KDIM + t * DIN);
    const uint4* ps = (const uint4*)packed;
    #pragma unroll
    for (int q = 0; q < 4; q++) Srow[q] = ps[q];
    if (t < DIN) g_Sx[(size_t)n * DIN + t] = __float2half_rn(sxa);
}

// ---------------- fp16 mma GEMM: out = relu([S|Sx|x] @ Wt^T + bias) -----------
// Block: 64 M-rows, 64 N-cols, 8 warps in 4x2 grid, each 16(M)x32(N).
// K tiled by 32 halfs, 3-stage cp.async, pitch 40 halfs (80B, conflict-free).
#define MT 64
#define PITCHH 40
#define A_STAGE (MT * PITCHH)           // 2560 halfs
#define B_STAGE (DOUT * PITCHH)         // 2560 halfs
#define STAGE_H (A_STAGE + B_STAGE)
#define NS 3
#define GEMM_SMEM (NS * STAGE_H * 2)

__device__ __forceinline__ void load_tile(int t, uint32_t sAu, uint32_t sBu, int m0, int n_nodes) {
    int tid = threadIdx.x;
    int k0 = t * 32;
    // A: 64 rows x 32 halfs; 4 threads/row, 8 halfs (16B) each
    {
        int r = tid >> 2, c0 = (tid & 3) * 8;
        int m = m0 + r;
        if (m >= n_nodes) m = n_nodes - 1;
        const __half* g;
        if (t < 128)       g = g_S  + (size_t)m * KDIM + k0 + c0;
        else if (t == 128) g = g_Sx + (size_t)m * DIN + c0;
        else               g = g_xh + (size_t)m * DIN + c0;
        cp16(sAu + (r * PITCHH + c0) * 2, g);
    }
    // B: 64 n-rows x 32 halfs
    {
        int nr = tid >> 2, c0 = (tid & 3) * 8;
        cp16(sBu + (nr * PITCHH + c0) * 2, g_Wt + (size_t)nr * KTOT + k0 + c0);
    }
}

__global__ __launch_bounds__(256) void gemm_mma_kernel(const float* __restrict__ bias,
                                                       float* __restrict__ out, int n_nodes) {
    extern __shared__ __half smem[];
    uint32_t smem_u = smem_to_u32(smem);
    int tid = threadIdx.x, wid = tid >> 5, lane = tid & 31;
    int wm = wid >> 1, wn = wid & 1;     // 4 x 2 warp grid
    int gid = lane >> 2, tig = lane & 3;
    int m0 = blockIdx.x * MT;

    float acc[4][4];
    #pragma unroll
    for (int nt = 0; nt < 4; nt++)
        #pragma unroll
        for (int r = 0; r < 4; r++) acc[nt][r] = 0.f;

    #pragma unroll
    for (int t = 0; t < NS - 1; t++) {
        load_tile(t, smem_u + t * STAGE_H * 2, smem_u + (t * STAGE_H + A_STAGE) * 2, m0, n_nodes);
        CP_COMMIT();
    }

    for (int t = 0; t < NTILES; t++) {
        asm volatile("cp.async.wait_group %0;" :: "n"(NS - 2) : "memory");
        __syncthreads();
        int tn = t + NS - 1;
        if (tn < NTILES) {
            int s = tn % NS;
            load_tile(tn, smem_u + s * STAGE_H * 2, smem_u + (s * STAGE_H + A_STAGE) * 2, m0, n_nodes);
        }
        CP_COMMIT();

        const __half* As = smem + (t % NS) * STAGE_H;
        const __half* Bs = As + A_STAGE;
        #pragma unroll
        for (int kc = 0; kc < 2; kc++) {
            int col = kc * 16 + 2 * tig;
            uint32_t a[4];
            {
                int r0 = wm * 16 + gid;
                a[0] = *(const uint32_t*)&As[r0 * PITCHH + col];
                a[1] = *(const uint32_t*)&As[(r0 + 8) * PITCHH + col];
                a[2] = *(const uint32_t*)&As[r0 * PITCHH + col + 8];
                a[3] = *(const uint32_t*)&As[(r0 + 8) * PITCHH + col + 8];
            }
            #pragma unroll
            for (int nt = 0; nt < 4; nt++) {
                int n0 = wn * 32 + nt * 8 + gid;
                uint32_t b[2];
                b[0] = *(const uint32_t*)&Bs[n0 * PITCHH + col];
                b[1] = *(const uint32_t*)&Bs[n0 * PITCHH + col + 8];
                mma_f16(acc[nt], a, b);
            }
        }
        __syncthreads();
    }

    // epilogue: bias + relu, fragment layout m16n8
    #pragma unroll
    for (int nt = 0; nt < 4; nt++) {
        int o = wn * 32 + nt * 8 + tig * 2;
        float b0 = __ldg(&bias[o]), b1 = __ldg(&bias[o + 1]);
        #pragma unroll
        for (int half_ = 0; half_ < 2; half_++) {
            int n = m0 + wm * 16 + gid + half_ * 8;
            if (n < n_nodes) {
                float2 v;
                v.x = fmaxf(acc[nt][2 * half_ + 0] + b0, 0.f);
                v.y = fmaxf(acc[nt][2 * half_ + 1] + b1, 0.f);
                *(float2*)(out + (size_t)n * DOUT + o) = v;
            }
        }
    }
}

// ---------------- launch ------------------------------------------------------
extern "C" void kernel_launch(void* const* d_in, const int* in_sizes, int n_in,
                              void* d_out, int out_size) {
    const float* x    = (const float*)d_in[0];
    const void*  ei   = d_in[1];
    const float* attr = (const float*)d_in[2];
    const float* W1   = (const float*)d_in[3];
    const float* b1   = (const float*)d_in[4];
    const float* W2   = (const float*)d_in[5];
    const float* b2   = (const float*)d_in[6];
    const float* root = (const float*)d_in[7];
    const float* bias = (const float*)d_in[8];
    float* out = (float*)d_out;

    int N = in_sizes[0] / DIN;
    int E = in_sizes[2] / BFD;
    if (N > NMAX) N = NMAX;
    if (E > EMAX) E = EMAX;

    void* degp = nullptr;
    cudaGetSymbolAddress(&degp, g_deg);
    cudaMemsetAsync(degp, 0, (size_t)N * sizeof(int));

    static int smem_set = 0;
    if (!smem_set) {
        cudaFuncSetAttribute(gemm_mma_kernel, cudaFuncAttributeMaxDynamicSharedMemorySize, GEMM_SMEM);
        smem_set = 1;
    }

    decode_count_kernel<<<264, 256>>>(ei, E);
    scan_kernel<<<1, 1024>>>(N);
    scatter_kernel<<<264, 256>>>(E);
    h_kernel<<<512, 256>>>(attr, W1, b1, E);
    wt_kernel<<<dim3(NTILES, 2), dim3(32, 32)>>>(W2, b2, root);
    xh_kernel<<<(N * DIN + 255) / 256, 256>>>(x, N * DIN);
    sbuild_kernel<<<N, 128>>>(x, N);
    gemm_mma_kernel<<<(N + MT - 1) / MT, 256, GEMM_SMEM>>>(bias, out, N);
}

// round 11
// speedup vs baseline: 1.7793x; 1.1786x over previous
#include <cuda_runtime.h>
#include <cuda_fp16.h>
#include <cstdint>
#include <cstddef>

// Problem constants
#define NMAX 10000
#define EMAX 160000
#define DIN 32
#define DOUT 64
#define DHID 128
#define BFD 13
#define KDIM (DHID * DIN)      // 4096
#define KTOT (KDIM + 2 * DIN)  // 4160 = S | Sx | x
#define NTILES (KTOT / 32)     // 130 k-tiles of 32 halfs

// ---------------- scratch (device globals; no allocations allowed) ------------
__device__ int    g_deg[NMAX];
__device__ int    g_rowptr[NMAX + 1];
__device__ int    g_cursor[NMAX];
__device__ int    g_src[EMAX];
__device__ int    g_dst[EMAX];
__device__ int    g_pos[EMAX];           // edge -> CSR slot
__device__ int    g_csr_src[EMAX];
__device__ __half g_attr16[(size_t)EMAX * 16];  // 5 MB, CSR order, K padded to 16
__device__ __half g_W1t16[DHID * 16];           // B operand: [128 n][16 k]
__device__ __half g_h[(size_t)EMAX * DHID];     // 41 MB, CSR order
__device__ __half g_S[(size_t)NMAX * KDIM];     // 82 MB
__device__ __half g_Sx[(size_t)NMAX * DIN];
__device__ __half g_xh[(size_t)NMAX * DIN];
__device__ __half g_Wt[(size_t)DOUT * KTOT];    // B^T: [64][4160]

// ---------------- small PTX helpers -------------------------------------------
__device__ __forceinline__ uint32_t smem_to_u32(const void* p) {
    uint32_t a;
    asm("{ .reg .u64 t; cvta.to.shared.u64 t, %1; cvt.u32.u64 %0, t; }" : "=r"(a) : "l"(p));
    return a;
}
__device__ __forceinline__ void cp16(uint32_t saddr, const void* g) {
    asm volatile("cp.async.cg.shared.global [%0], [%1], 16;" :: "r"(saddr), "l"(g));
}
#define CP_COMMIT() asm volatile("cp.async.commit_group;" ::: "memory")

__device__ __forceinline__ void mma_f16(float* d, const uint32_t* a, const uint32_t* b) {
    asm volatile("mma.sync.aligned.m16n8k16.row.col.f32.f16.f16.f32 "
        "{%0,%1,%2,%3}, {%4,%5,%6,%7}, {%8,%9}, {%0,%1,%2,%3};"
        : "+f"(d[0]), "+f"(d[1]), "+f"(d[2]), "+f"(d[3])
        : "r"(a[0]), "r"(a[1]), "r"(a[2]), "r"(a[3]), "r"(b[0]), "r"(b[1]));
}

// ---------------- decode + degree count (detect int64 inline) -----------------
__global__ void decode_count_kernel(const void* ei, int E) {
    __shared__ int s64;
    if (threadIdx.x == 0) {
        const int* w = (const int*)ei;
        long long s = 0;
        #pragma unroll 8
        for (int i = 0; i < 64; i++) s += w[2 * i + 1];
        s64 = (s == 0) ? 1 : 0;
    }
    __syncthreads();
    bool is64 = (s64 != 0);
    int i = blockIdx.x * blockDim.x + threadIdx.x;
    int stride = gridDim.x * blockDim.x;
    for (int e = i; e < E; e += stride) {
        int s, d;
        if (is64) {
            const long long* p = (const long long*)ei;
            s = (int)p[e]; d = (int)p[E + e];
        } else {
            const int* p = (const int*)ei;
            s = p[e]; d = p[E + e];
        }
        g_src[e] = s;
        g_dst[e] = d;
        atomicAdd(&g_deg[d], 1);
    }
}

// ---------------- single-block exclusive scan over degrees --------------------
__global__ __launch_bounds__(1024) void scan_kernel(int n) {
    __shared__ int wsum[32];
    __shared__ int carry_s;
    int tid = threadIdx.x, lane = tid & 31, wid = tid >> 5;
    if (tid == 0) carry_s = 0;
    __syncthreads();
    for (int base = 0; base < n; base += 1024) {
        int i = base + tid;
        int v = (i < n) ? g_deg[i] : 0;
        int incl = v;
        #pragma unroll
        for (int d = 1; d < 32; d <<= 1) {
            int y = __shfl_up_sync(0xffffffffu, incl, d);
            if (lane >= d) incl += y;
        }
        if (lane == 31) wsum[wid] = incl;
        __syncthreads();
        if (wid == 0) {
            int s = wsum[lane];
            #pragma unroll
            for (int d = 1; d < 32; d <<= 1) {
                int y = __shfl_up_sync(0xffffffffu, s, d);
                if (lane >= d) s += y;
            }
            wsum[lane] = s;
        }
        __syncthreads();
        int excl = incl - v + ((wid > 0) ? wsum[wid - 1] : 0) + carry_s;
        if (i < n) { g_rowptr[i] = excl; g_cursor[i] = excl; }
        int total = wsum[31];
        __syncthreads();
        if (tid == 0) carry_s += total;
        __syncthreads();
    }
    if (tid == 0) g_rowptr[n] = carry_s;
}

// ---------------- scatter edges into dst-CSR ----------------------------------
__global__ void scatter_kernel(int E) {
    int i = blockIdx.x * blockDim.x + threadIdx.x;
    int stride = gridDim.x * blockDim.x;
    for (int e = i; e < E; e += stride) {
        int d = g_dst[e];
        int pos = atomicAdd(&g_cursor[d], 1);
        g_csr_src[pos] = g_src[e];
        g_pos[e] = pos;
    }
}

// ---------------- attr -> fp16 [E][16], CSR order -----------------------------
__global__ __launch_bounds__(256) void attr16_kernel(const float* __restrict__ attr, int E) {
    __shared__ float s[256 * BFD];
    int base = blockIdx.x * 256;
    int cnt = E - base;
    if (cnt > 256) cnt = 256;
    if (cnt <= 0) return;
    for (int j = threadIdx.x; j < cnt * BFD; j += 256)
        s[j] = attr[(size_t)base * BFD + j];
    __syncthreads();
    int tid = threadIdx.x;
    if (tid < cnt) {
        int e = base + tid;
        const float* a = s + tid * BFD;
        __half2 p[8];
        #pragma unroll
        for (int q = 0; q < 6; q++) p[q] = __floats2half2_rn(a[2 * q], a[2 * q + 1]);
        p[6] = __floats2half2_rn(a[12], 0.f);
        p[7] = __floats2half2_rn(0.f, 0.f);
        uint4* dst = (uint4*)(g_attr16 + (size_t)g_pos[e] * 16);
        const uint4* ps = (const uint4*)p;
        dst[0] = ps[0];
        dst[1] = ps[1];
    }
}

// ---------------- W1 -> fp16 B operand [128 n][16 k] --------------------------
__global__ void w1t16_kernel(const float* __restrict__ W1) {
    int i = blockIdx.x * 256 + threadIdx.x;
    if (i < DHID * 16) {
        int n = i >> 4, k = i & 15;
        g_W1t16[i] = (k < BFD) ? __float2half_rn(W1[k * DHID + n]) : __float2half_rn(0.f);
    }
}

// ---------------- h = relu(attr16 @ W1t16^T + b1) via m16n8k16 ----------------
// Warp handles 16 edges x 128 cols; B fragments register-resident.
__global__ __launch_bounds__(256) void hmma_kernel(const float* __restrict__ b1, int E) {
    int tid = threadIdx.x, wid = tid >> 5, lane = tid & 31;
    int gid = lane >> 2, tig = lane & 3;
    int e0 = (blockIdx.x * 8 + wid) * 16;
    if (e0 >= E) return;
    uint32_t br[16][2];
    #pragma unroll
    for (int nt = 0; nt < 16; nt++) {
        int n0 = nt * 8 + gid;
        br[nt][0] = *(const uint32_t*)&g_W1t16[n0 * 16 + 2 * tig];
        br[nt][1] = *(const uint32_t*)&g_W1t16[n0 * 16 + 2 * tig + 8];
    }
    int r0 = e0 + gid, r1 = r0 + 8;
    int r0c = (r0 < E) ? r0 : E - 1;
    int r1c = (r1 < E) ? r1 : E - 1;
    uint32_t a[4];
    a[0] = *(const uint32_t*)&g_attr16[(size_t)r0c * 16 + 2 * tig];
    a[1] = *(const uint32_t*)&g_attr16[(size_t)r1c * 16 + 2 * tig];
    a[2] = *(const uint32_t*)&g_attr16[(size_t)r0c * 16 + 2 * tig + 8];
    a[3] = *(const uint32_t*)&g_attr16[(size_t)r1c * 16 + 2 * tig + 8];
    #pragma unroll
    for (int nt = 0; nt < 16; nt++) {
        float c[4] = {0.f, 0.f, 0.f, 0.f};
        mma_f16(c, a, br[nt]);
        int col = nt * 8 + 2 * tig;
        float bb0 = __ldg(&b1[col]), bb1 = __ldg(&b1[col + 1]);
        if (r0 < E)
            *(__half2*)&g_h[(size_t)r0 * DHID + col] =
                __floats2half2_rn(fmaxf(c[0] + bb0, 0.f), fmaxf(c[1] + bb1, 0.f));
        if (r1 < E)
            *(__half2*)&g_h[(size_t)r1 * DHID + col] =
                __floats2half2_rn(fmaxf(c[2] + bb0, 0.f), fmaxf(c[3] + bb1, 0.f));
    }
}

// ---------------- build g_Wt[o][k] = B[k][o] (half), B = [W2 | b2 | root] -----
__global__ __launch_bounds__(1024) void wt_kernel(const float* __restrict__ W2,
                                                  const float* __restrict__ b2,
                                                  const float* __restrict__ root) {
    __shared__ float tile[32][33];
    int k0 = blockIdx.x * 32, n0 = blockIdx.y * 32;
    int tx = threadIdx.x, ty = threadIdx.y;
    int k = k0 + ty, n = n0 + tx;
    float v;
    if (k < KDIM)            v = W2[(size_t)k * DOUT + n];
    else if (k < KDIM + DIN) v = b2[(size_t)(k - KDIM) * DOUT + n];
    else                     v = root[(size_t)(k - KDIM - DIN) * DOUT + n];
    tile[ty][tx] = v;
    __syncthreads();
    g_Wt[(size_t)(n0 + ty) * KTOT + k0 + tx] = __float2half_rn(tile[tx][ty]);
}

// ---------------- x -> half ----------------------------------------------------
__global__ void xh_kernel(const float* __restrict__ x, int total) {
    int i = blockIdx.x * blockDim.x + threadIdx.x;
    if (i < total) g_xh[i] = __float2half_rn(x[i]);
}

// ---------------- S[n,k,i] = sum_{e->n} h_e[k] * x_src[i];  Sx[n,i] -----------
__global__ __launch_bounds__(128) void sbuild_kernel(const float* __restrict__ x, int n_nodes) {
    int n = blockIdx.x;
    if (n >= n_nodes) return;
    int t = threadIdx.x;   // 0..127 == k
    __shared__ float xs[4][DIN];
    float acc[DIN];
    #pragma unroll
    for (int i = 0; i < DIN; i++) acc[i] = 0.f;
    float sxa = 0.f;
    int beg = g_rowptr[n], end = g_rowptr[n + 1];
    int idx = beg;
    for (; idx + 4 <= end; idx += 4) {
        int j = t >> 5, i = t & 31;
        int srcj = g_csr_src[idx + j];
        xs[j][i] = x[(size_t)srcj * DIN + i];
        float hv0 = __half2float(g_h[(size_t)(idx + 0) * DHID + t]);
        float hv1 = __half2float(g_h[(size_t)(idx + 1) * DHID + t]);
        float hv2 = __half2float(g_h[(size_t)(idx + 2) * DHID + t]);
        float hv3 = __half2float(g_h[(size_t)(idx + 3) * DHID + t]);
        __syncthreads();
        #pragma unroll
        for (int c = 0; c < DIN; c++)
            acc[c] += hv0 * xs[0][c] + hv1 * xs[1][c] + hv2 * xs[2][c] + hv3 * xs[3][c];
        if (t < DIN) sxa += xs[0][t] + xs[1][t] + xs[2][t] + xs[3][t];
        __syncthreads();
    }
    for (; idx < end; idx++) {
        if (t < DIN) xs[0][t] = x[(size_t)g_csr_src[idx] * DIN + t];
        float hv = __half2float(g_h[(size_t)idx * DHID + t]);
        __syncthreads();
        #pragma unroll
        for (int c = 0; c < DIN; c++) acc[c] += hv * xs[0][c];
        if (t < DIN) sxa += xs[0][t];
        __syncthreads();
    }
    // store 32 halfs = 16 x half2 via vector stores
    __half2 packed[16];
    #pragma unroll
    for (int q = 0; q < 16; q++)
        packed[q] = __floats2half2_rn(acc[2 * q], acc[2 * q + 1]);
    uint4* Srow = (uint4*)(g_S + (size_t)n * KDIM + t * DIN);
    const uint4* ps = (const uint4*)packed;
    #pragma unroll
    for (int q = 0; q < 4; q++) Srow[q] = ps[q];
    if (t < DIN) g_Sx[(size_t)n * DIN + t] = __float2half_rn(sxa);
}

// ---------------- fp16 mma GEMM: out = relu([S|Sx|x] @ Wt^T + bias) -----------
#define MT 64
#define PITCHH 40
#define A_STAGE (MT * PITCHH)           // 2560 halfs
#define B_STAGE (DOUT * PITCHH)         // 2560 halfs
#define STAGE_H (A_STAGE + B_STAGE)
#define NS 3
#define GEMM_SMEM (NS * STAGE_H * 2)

__device__ __forceinline__ void load_tile(int t, uint32_t sAu, uint32_t sBu, int m0, int n_nodes) {
    int tid = threadIdx.x;
    int k0 = t * 32;
    {
        int r = tid >> 2, c0 = (tid & 3) * 8;
        int m = m0 + r;
        if (m >= n_nodes) m = n_nodes - 1;
        const __half* g;
        if (t < 128)       g = g_S  + (size_t)m * KDIM + k0 + c0;
        else if (t == 128) g = g_Sx + (size_t)m * DIN + c0;
        else               g = g_xh + (size_t)m * DIN + c0;
        cp16(sAu + (r * PITCHH + c0) * 2, g);
    }
    {
        int nr = tid >> 2, c0 = (tid & 3) * 8;
        cp16(sBu + (nr * PITCHH + c0) * 2, g_Wt + (size_t)nr * KTOT + k0 + c0);
    }
}

__global__ __launch_bounds__(256) void gemm_mma_kernel(const float* __restrict__ bias,
                                                       float* __restrict__ out, int n_nodes) {
    extern __shared__ __half smem[];
    uint32_t smem_u = smem_to_u32(smem);
    int tid = threadIdx.x, wid = tid >> 5, lane = tid & 31;
    int wm = wid >> 1, wn = wid & 1;     // 4 x 2 warp grid
    int gid = lane >> 2, tig = lane & 3;
    int m0 = blockIdx.x * MT;

    float acc[4][4];
    #pragma unroll
    for (int nt = 0; nt < 4; nt++)
        #pragma unroll
        for (int r = 0; r < 4; r++) acc[nt][r] = 0.f;

    #pragma unroll
    for (int t = 0; t < NS - 1; t++) {
        load_tile(t, smem_u + t * STAGE_H * 2, smem_u + (t * STAGE_H + A_STAGE) * 2, m0, n_nodes);
        CP_COMMIT();
    }

    for (int t = 0; t < NTILES; t++) {
        asm volatile("cp.async.wait_group %0;" :: "n"(NS - 2) : "memory");
        __syncthreads();
        int tn = t + NS - 1;
        if (tn < NTILES) {
            int s = tn % NS;
            load_tile(tn, smem_u + s * STAGE_H * 2, smem_u + (s * STAGE_H + A_STAGE) * 2, m0, n_nodes);
        }
        CP_COMMIT();

        const __half* As = smem + (t % NS) * STAGE_H;
        const __half* Bs = As + A_STAGE;
        #pragma unroll
        for (int kc = 0; kc < 2; kc++) {
            int col = kc * 16 + 2 * tig;
            uint32_t a[4];
            {
                int r0 = wm * 16 + gid;
                a[0] = *(const uint32_t*)&As[r0 * PITCHH + col];
                a[1] = *(const uint32_t*)&As[(r0 + 8) * PITCHH + col];
                a[2] = *(const uint32_t*)&As[r0 * PITCHH + col + 8];
                a[3] = *(const uint32_t*)&As[(r0 + 8) * PITCHH + col + 8];
            }
            #pragma unroll
            for (int nt = 0; nt < 4; nt++) {
                int n0 = wn * 32 + nt * 8 + gid;
                uint32_t b[2];
                b[0] = *(const uint32_t*)&Bs[n0 * PITCHH + col];
                b[1] = *(const uint32_t*)&Bs[n0 * PITCHH + col + 8];
                mma_f16(acc[nt], a, b);
            }
        }
        __syncthreads();
    }

    #pragma unroll
    for (int nt = 0; nt < 4; nt++) {
        int o = wn * 32 + nt * 8 + tig * 2;
        float b0 = __ldg(&bias[o]), b1 = __ldg(&bias[o + 1]);
        #pragma unroll
        for (int half_ = 0; half_ < 2; half_++) {
            int n = m0 + wm * 16 + gid + half_ * 8;
            if (n < n_nodes) {
                float2 v;
                v.x = fmaxf(acc[nt][2 * half_ + 0] + b0, 0.f);
                v.y = fmaxf(acc[nt][2 * half_ + 1] + b1, 0.f);
                *(float2*)(out + (size_t)n * DOUT + o) = v;
            }
        }
    }
}

// ---------------- launch ------------------------------------------------------
extern "C" void kernel_launch(void* const* d_in, const int* in_sizes, int n_in,
                              void* d_out, int out_size) {
    const float* x    = (const float*)d_in[0];
    const void*  ei   = d_in[1];
    const float* attr = (const float*)d_in[2];
    const float* W1   = (const float*)d_in[3];
    const float* b1   = (const float*)d_in[4];
    const float* W2   = (const float*)d_in[5];
    const float* b2   = (const float*)d_in[6];
    const float* root = (const float*)d_in[7];
    const float* bias = (const float*)d_in[8];
    float* out = (float*)d_out;

    int N = in_sizes[0] / DIN;
    int E = in_sizes[2] / BFD;
    if (N > NMAX) N = NMAX;
    if (E > EMAX) E = EMAX;

    void* degp = nullptr;
    cudaGetSymbolAddress(&degp, g_deg);
    cudaMemsetAsync(degp, 0, (size_t)N * sizeof(int));

    static int smem_set = 0;
    if (!smem_set) {
        cudaFuncSetAttribute(gemm_mma_kernel, cudaFuncAttributeMaxDynamicSharedMemorySize, GEMM_SMEM);
        smem_set = 1;
    }

    decode_count_kernel<<<264, 256>>>(ei, E);
    scan_kernel<<<1, 1024>>>(N);
    scatter_kernel<<<264, 256>>>(E);
    attr16_kernel<<<(E + 255) / 256, 256>>>(attr, E);
    w1t16_kernel<<<(DHID * 16 + 255) / 256, 256>>>(W1);
    hmma_kernel<<<(E + 127) / 128, 256>>>(b1, E);
    wt_kernel<<<dim3(NTILES, 2), dim3(32, 32)>>>(W2, b2, root);
    xh_kernel<<<(N * DIN + 255) / 256, 256>>>(x, N * DIN);
    sbuild_kernel<<<N, 128>>>(x, N);
    gemm_mma_kernel<<<(N + MT - 1) / MT, 256, GEMM_SMEM>>>(bias, out, N);
}

// round 12
// speedup vs baseline: 2.2165x; 1.2457x over previous
#include <cuda_runtime.h>
#include <cuda_fp16.h>
#include <cstdint>
#include <cstddef>

// Problem constants
#define NMAX 10000
#define EMAX 160000
#define DIN 32
#define DOUT 64
#define DHID 128
#define BFD 13
#define KDIM (DHID * DIN)      // 4096
#define KTOT (KDIM + 2 * DIN)  // 4160 = S | Sx | x
#define NTILES (KTOT / 32)     // 130 k-tiles of 32 halfs

// ---------------- scratch (device globals; no allocations allowed) ------------
__device__ int    g_deg[NMAX];
__device__ int    g_rowptr[NMAX + 1];
__device__ int    g_cursor[NMAX];
__device__ int    g_src[EMAX];
__device__ int    g_dst[EMAX];
__device__ int    g_pos[EMAX];           // edge -> CSR slot
__device__ int    g_csr_src[EMAX];
__device__ __half g_attr16[(size_t)EMAX * 16];  // 5 MB, CSR order, K padded to 16
__device__ __half g_W1t16[DHID * 16];           // B operand: [128 n][16 k]
__device__ __half g_h[(size_t)EMAX * DHID];     // 41 MB, CSR order
__device__ __half g_S[(size_t)NMAX * KDIM];     // 82 MB
__device__ __half g_Sx[(size_t)NMAX * DIN];
__device__ __half g_xh[(size_t)NMAX * DIN];
__device__ __half g_Wt[(size_t)DOUT * KTOT];    // B^T: [64][4160]

// ---------------- small PTX helpers -------------------------------------------
__device__ __forceinline__ uint32_t smem_to_u32(const void* p) {
    uint32_t a;
    asm("{ .reg .u64 t; cvta.to.shared.u64 t, %1; cvt.u32.u64 %0, t; }" : "=r"(a) : "l"(p));
    return a;
}
__device__ __forceinline__ void cp16(uint32_t saddr, const void* g) {
    asm volatile("cp.async.cg.shared.global [%0], [%1], 16;" :: "r"(saddr), "l"(g));
}
#define CP_COMMIT() asm volatile("cp.async.commit_group;" ::: "memory")

__device__ __forceinline__ void mma_f16(float* d, const uint32_t* a, const uint32_t* b) {
    asm volatile("mma.sync.aligned.m16n8k16.row.col.f32.f16.f16.f32 "
        "{%0,%1,%2,%3}, {%4,%5,%6,%7}, {%8,%9}, {%0,%1,%2,%3};"
        : "+f"(d[0]), "+f"(d[1]), "+f"(d[2]), "+f"(d[3])
        : "r"(a[0]), "r"(a[1]), "r"(a[2]), "r"(a[3]), "r"(b[0]), "r"(b[1]));
}
__device__ __forceinline__ void ldmatrix_x4_trans(uint32_t* r, uint32_t saddr) {
    asm volatile("ldmatrix.sync.aligned.m8n8.x4.trans.shared.b16 {%0,%1,%2,%3}, [%4];"
        : "=r"(r[0]), "=r"(r[1]), "=r"(r[2]), "=r"(r[3]) : "r"(saddr));
}

// ---------------- decode + degree count (detect int64 inline) -----------------
__global__ void decode_count_kernel(const void* ei, int E) {
    __shared__ int s64;
    if (threadIdx.x == 0) {
        const int* w = (const int*)ei;
        long long s = 0;
        #pragma unroll 8
        for (int i = 0; i < 64; i++) s += w[2 * i + 1];
        s64 = (s == 0) ? 1 : 0;
    }
    __syncthreads();
    bool is64 = (s64 != 0);
    int i = blockIdx.x * blockDim.x + threadIdx.x;
    int stride = gridDim.x * blockDim.x;
    for (int e = i; e < E; e += stride) {
        int s, d;
        if (is64) {
            const long long* p = (const long long*)ei;
            s = (int)p[e]; d = (int)p[E + e];
        } else {
            const int* p = (const int*)ei;
            s = p[e]; d = p[E + e];
        }
        g_src[e] = s;
        g_dst[e] = d;
        atomicAdd(&g_deg[d], 1);
    }
}

// ---------------- single-block exclusive scan over degrees --------------------
__global__ __launch_bounds__(1024) void scan_kernel(int n) {
    __shared__ int wsum[32];
    __shared__ int carry_s;
    int tid = threadIdx.x, lane = tid & 31, wid = tid >> 5;
    if (tid == 0) carry_s = 0;
    __syncthreads();
    for (int base = 0; base < n; base += 1024) {
        int i = base + tid;
        int v = (i < n) ? g_deg[i] : 0;
        int incl = v;
        #pragma unroll
        for (int d = 1; d < 32; d <<= 1) {
            int y = __shfl_up_sync(0xffffffffu, incl, d);
            if (lane >= d) incl += y;
        }
        if (lane == 31) wsum[wid] = incl;
        __syncthreads();
        if (wid == 0) {
            int s = wsum[lane];
            #pragma unroll
            for (int d = 1; d < 32; d <<= 1) {
                int y = __shfl_up_sync(0xffffffffu, s, d);
                if (lane >= d) s += y;
            }
            wsum[lane] = s;
        }
        __syncthreads();
        int excl = incl - v + ((wid > 0) ? wsum[wid - 1] : 0) + carry_s;
        if (i < n) { g_rowptr[i] = excl; g_cursor[i] = excl; }
        int total = wsum[31];
        __syncthreads();
        if (tid == 0) carry_s += total;
        __syncthreads();
    }
    if (tid == 0) g_rowptr[n] = carry_s;
}

// ---------------- scatter edges into dst-CSR ----------------------------------
__global__ void scatter_kernel(int E) {
    int i = blockIdx.x * blockDim.x + threadIdx.x;
    int stride = gridDim.x * blockDim.x;
    for (int e = i; e < E; e += stride) {
        int d = g_dst[e];
        int pos = atomicAdd(&g_cursor[d], 1);
        g_csr_src[pos] = g_src[e];
        g_pos[e] = pos;
    }
}

// ---------------- attr -> fp16 [E][16], CSR order -----------------------------
__global__ __launch_bounds__(256) void attr16_kernel(const float* __restrict__ attr, int E) {
    __shared__ float s[256 * BFD];
    int base = blockIdx.x * 256;
    int cnt = E - base;
    if (cnt > 256) cnt = 256;
    if (cnt <= 0) return;
    for (int j = threadIdx.x; j < cnt * BFD; j += 256)
        s[j] = attr[(size_t)base * BFD + j];
    __syncthreads();
    int tid = threadIdx.x;
    if (tid < cnt) {
        int e = base + tid;
        const float* a = s + tid * BFD;
        __half2 p[8];
        #pragma unroll
        for (int q = 0; q < 6; q++) p[q] = __floats2half2_rn(a[2 * q], a[2 * q + 1]);
        p[6] = __floats2half2_rn(a[12], 0.f);
        p[7] = __floats2half2_rn(0.f, 0.f);
        uint4* dst = (uint4*)(g_attr16 + (size_t)g_pos[e] * 16);
        const uint4* ps = (const uint4*)p;
        dst[0] = ps[0];
        dst[1] = ps[1];
    }
}

// ---------------- W1 -> fp16 B operand [128 n][16 k] --------------------------
__global__ void w1t16_kernel(const float* __restrict__ W1) {
    int i = blockIdx.x * 256 + threadIdx.x;
    if (i < DHID * 16) {
        int n = i >> 4, k = i & 15;
        g_W1t16[i] = (k < BFD) ? __float2half_rn(W1[k * DHID + n]) : __float2half_rn(0.f);
    }
}

// ---------------- h = relu(attr16 @ W1t16^T + b1) via m16n8k16 ----------------
__global__ __launch_bounds__(256) void hmma_kernel(const float* __restrict__ b1, int E) {
    int tid = threadIdx.x, wid = tid >> 5, lane = tid & 31;
    int gid = lane >> 2, tig = lane & 3;
    int e0 = (blockIdx.x * 8 + wid) * 16;
    if (e0 >= E) return;
    uint32_t br[16][2];
    #pragma unroll
    for (int nt = 0; nt < 16; nt++) {
        int n0 = nt * 8 + gid;
        br[nt][0] = *(const uint32_t*)&g_W1t16[n0 * 16 + 2 * tig];
        br[nt][1] = *(const uint32_t*)&g_W1t16[n0 * 16 + 2 * tig + 8];
    }
    int r0 = e0 + gid, r1 = r0 + 8;
    int r0c = (r0 < E) ? r0 : E - 1;
    int r1c = (r1 < E) ? r1 : E - 1;
    uint32_t a[4];
    a[0] = *(const uint32_t*)&g_attr16[(size_t)r0c * 16 + 2 * tig];
    a[1] = *(const uint32_t*)&g_attr16[(size_t)r1c * 16 + 2 * tig];
    a[2] = *(const uint32_t*)&g_attr16[(size_t)r0c * 16 + 2 * tig + 8];
    a[3] = *(const uint32_t*)&g_attr16[(size_t)r1c * 16 + 2 * tig + 8];
    #pragma unroll
    for (int nt = 0; nt < 16; nt++) {
        float c[4] = {0.f, 0.f, 0.f, 0.f};
        mma_f16(c, a, br[nt]);
        int col = nt * 8 + 2 * tig;
        float bb0 = __ldg(&b1[col]), bb1 = __ldg(&b1[col + 1]);
        if (r0 < E)
            *(__half2*)&g_h[(size_t)r0 * DHID + col] =
                __floats2half2_rn(fmaxf(c[0] + bb0, 0.f), fmaxf(c[1] + bb1, 0.f));
        if (r1 < E)
            *(__half2*)&g_h[(size_t)r1 * DHID + col] =
                __floats2half2_rn(fmaxf(c[2] + bb0, 0.f), fmaxf(c[3] + bb1, 0.f));
    }
}

// ---------------- build g_Wt[o][k] = B[k][o] (half), B = [W2 | b2 | root] -----
__global__ __launch_bounds__(1024) void wt_kernel(const float* __restrict__ W2,
                                                  const float* __restrict__ b2,
                                                  const float* __restrict__ root) {
    __shared__ float tile[32][33];
    int k0 = blockIdx.x * 32, n0 = blockIdx.y * 32;
    int tx = threadIdx.x, ty = threadIdx.y;
    int k = k0 + ty, n = n0 + tx;
    float v;
    if (k < KDIM)            v = W2[(size_t)k * DOUT + n];
    else if (k < KDIM + DIN) v = b2[(size_t)(k - KDIM) * DOUT + n];
    else                     v = root[(size_t)(k - KDIM - DIN) * DOUT + n];
    tile[ty][tx] = v;
    __syncthreads();
    g_Wt[(size_t)(n0 + ty) * KTOT + k0 + tx] = __float2half_rn(tile[tx][ty]);
}

// ---------------- x -> half ----------------------------------------------------
__global__ void xh_kernel(const float* __restrict__ x, int total) {
    int i = blockIdx.x * blockDim.x + threadIdx.x;
    if (i < total) g_xh[i] = __float2half_rn(x[i]);
}

// ---------------- tensor-core sbuild: S_n = H_n^T @ X_n per node --------------
// CTA = 1 node, 4 warps; warp w owns h-cols w*32..+31. K chunks of 16 edges.
#define HPITCH 136   // halfs per sh row (272B: ldmatrix rows hit distinct banks)
#define XPITCH 24    // halfs per Xt row (48B: conflict-free B LDS)
__global__ __launch_bounds__(128) void sbuild_tc_kernel(int n_nodes) {
    __shared__ __half sh[16 * HPITCH];   // h tile [e][col]
    __shared__ __half sx[32 * XPITCH];   // Xt [i][e]
    int n = blockIdx.x;
    if (n >= n_nodes) return;
    int tid = threadIdx.x, wid = tid >> 5, lane = tid & 31;
    int gid = lane >> 2, tig = lane & 3;
    uint32_t sh_u = smem_to_u32(sh);

    float acc[2][4][4];
    #pragma unroll
    for (int mt = 0; mt < 2; mt++)
        #pragma unroll
        for (int nt = 0; nt < 4; nt++)
            #pragma unroll
            for (int q = 0; q < 4; q++) acc[mt][nt][q] = 0.f;
    float sxa = 0.f;

    int beg = g_rowptr[n];
    int deg = g_rowptr[n + 1] - beg;

    for (int c0 = 0; c0 < deg; c0 += 16) {
        // stage h tile: thread t -> row r=t>>3, 16-half segment s=(t&7)*16
        {
            int r = tid >> 3, s = (tid & 7) * 16;
            uint4 z = make_uint4(0, 0, 0, 0);
            uint4 v0 = z, v1 = z;
            if (c0 + r < deg) {
                const uint4* src = (const uint4*)&g_h[(size_t)(beg + c0 + r) * DHID + s];
                v0 = src[0]; v1 = src[1];
            }
            *(uint4*)&sh[r * HPITCH + s] = v0;
            *(uint4*)&sh[r * HPITCH + s + 8] = v1;
        }
        // gather Xt: thread t -> edge j=t>>3, 4 i-values ci=(t&7)*4
        {
            int j = tid >> 3, ci = (tid & 7) * 4;
            __half vals[4];
            if (c0 + j < deg) {
                int srcn = g_csr_src[beg + c0 + j];
                *(uint2*)vals = *(const uint2*)&g_xh[(size_t)srcn * DIN + ci];
            } else {
                vals[0] = vals[1] = vals[2] = vals[3] = __float2half_rn(0.f);
            }
            #pragma unroll
            for (int q = 0; q < 4; q++) sx[(ci + q) * XPITCH + j] = vals[q];
        }
        __syncthreads();
        // Sx partial: warp 0, lane i sums its row of Xt
        if (tid < 32) {
            #pragma unroll
            for (int e2 = 0; e2 < 8; e2++) {
                __half2 hv = *(const __half2*)&sx[tid * XPITCH + 2 * e2];
                float2 f = __half22float2(hv);
                sxa += f.x + f.y;
            }
        }
        // B fragments from Xt
        uint32_t b[4][2];
        #pragma unroll
        for (int nt = 0; nt < 4; nt++) {
            int irow = nt * 8 + gid;
            b[nt][0] = *(const uint32_t*)&sx[irow * XPITCH + 2 * tig];
            b[nt][1] = *(const uint32_t*)&sx[irow * XPITCH + 2 * tig + 8];
        }
        // A fragments via ldmatrix.trans, then MMA
        int grp = lane >> 3, lr = lane & 7;
        int e_l = ((grp & 2) ? 8 : 0) + lr;
        int coff = (grp & 1) ? 8 : 0;
        #pragma unroll
        for (int mt = 0; mt < 2; mt++) {
            int mbase = wid * 32 + mt * 16;
            uint32_t a[4];
            ldmatrix_x4_trans(a, sh_u + (uint32_t)(e_l * HPITCH + mbase + coff) * 2);
            #pragma unroll
            for (int nt = 0; nt < 4; nt++) mma_f16(acc[mt][nt], a, b[nt]);
        }
        __syncthreads();
    }

    // store S (fp16) and Sx
    #pragma unroll
    for (int mt = 0; mt < 2; mt++) {
        #pragma unroll
        for (int nt = 0; nt < 4; nt++) {
            const float* c = acc[mt][nt];
            int m1 = wid * 32 + mt * 16 + gid;
            int i0 = nt * 8 + 2 * tig;
            *(__half2*)&g_S[(size_t)n * KDIM + m1 * DIN + i0] = __floats2half2_rn(c[0], c[1]);
            *(__half2*)&g_S[(size_t)n * KDIM + (m1 + 8) * DIN + i0] = __floats2half2_rn(c[2], c[3]);
        }
    }
    if (tid < 32) g_Sx[(size_t)n * DIN + tid] = __float2half_rn(sxa);
}

// ---------------- fp16 mma GEMM: out = relu([S|Sx|x] @ Wt^T + bias) -----------
#define MT 64
#define PITCHH 40
#define A_STAGE (MT * PITCHH)           // 2560 halfs
#define B_STAGE (DOUT * PITCHH)         // 2560 halfs
#define STAGE_H (A_STAGE + B_STAGE)
#define NS 3
#define GEMM_SMEM (NS * STAGE_H * 2)

__device__ __forceinline__ void load_tile(int t, uint32_t sAu, uint32_t sBu, int m0, int n_nodes) {
    int tid = threadIdx.x;
    int k0 = t * 32;
    {
        int r = tid >> 2, c0 = (tid & 3) * 8;
        int m = m0 + r;
        if (m >= n_nodes) m = n_nodes - 1;
        const __half* g;
        if (t < 128)       g = g_S  + (size_t)m * KDIM + k0 + c0;
        else if (t == 128) g = g_Sx + (size_t)m * DIN + c0;
        else               g = g_xh + (size_t)m * DIN + c0;
        cp16(sAu + (r * PITCHH + c0) * 2, g);
    }
    {
        int nr = tid >> 2, c0 = (tid & 3) * 8;
        cp16(sBu + (nr * PITCHH + c0) * 2, g_Wt + (size_t)nr * KTOT + k0 + c0);
    }
}

__global__ __launch_bounds__(256) void gemm_mma_kernel(const float* __restrict__ bias,
                                                       float* __restrict__ out, int n_nodes) {
    extern __shared__ __half smem[];
    uint32_t smem_u = smem_to_u32(smem);
    int tid = threadIdx.x, wid = tid >> 5, lane = tid & 31;
    int wm = wid >> 1, wn = wid & 1;     // 4 x 2 warp grid
    int gid = lane >> 2, tig = lane & 3;
    int m0 = blockIdx.x * MT;

    float acc[4][4];
    #pragma unroll
    for (int nt = 0; nt < 4; nt++)
        #pragma unroll
        for (int r = 0; r < 4; r++) acc[nt][r] = 0.f;

    #pragma unroll
    for (int t = 0; t < NS - 1; t++) {
        load_tile(t, smem_u + t * STAGE_H * 2, smem_u + (t * STAGE_H + A_STAGE) * 2, m0, n_nodes);
        CP_COMMIT();
    }

    for (int t = 0; t < NTILES; t++) {
        asm volatile("cp.async.wait_group %0;" :: "n"(NS - 2) : "memory");
        __syncthreads();
        int tn = t + NS - 1;
        if (tn < NTILES) {
            int s = tn % NS;
            load_tile(tn, smem_u + s * STAGE_H * 2, smem_u + (s * STAGE_H + A_STAGE) * 2, m0, n_nodes);
        }
        CP_COMMIT();

        const __half* As = smem + (t % NS) * STAGE_H;
        const __half* Bs = As + A_STAGE;
        #pragma unroll
        for (int kc = 0; kc < 2; kc++) {
            int col = kc * 16 + 2 * tig;
            uint32_t a[4];
            {
                int r0 = wm * 16 + gid;
                a[0] = *(const uint32_t*)&As[r0 * PITCHH + col];
                a[1] = *(const uint32_t*)&As[(r0 + 8) * PITCHH + col];
                a[2] = *(const uint32_t*)&As[r0 * PITCHH + col + 8];
                a[3] = *(const uint32_t*)&As[(r0 + 8) * PITCHH + col + 8];
            }
            #pragma unroll
            for (int nt = 0; nt < 4; nt++) {
                int n0 = wn * 32 + nt * 8 + gid;
                uint32_t b[2];
                b[0] = *(const uint32_t*)&Bs[n0 * PITCHH + col];
                b[1] = *(const uint32_t*)&Bs[n0 * PITCHH + col + 8];
                mma_f16(acc[nt], a, b);
            }
        }
        __syncthreads();
    }

    #pragma unroll
    for (int nt = 0; nt < 4; nt++) {
        int o = wn * 32 + nt * 8 + tig * 2;
        float b0 = __ldg(&bias[o]), b1 = __ldg(&bias[o + 1]);
        #pragma unroll
        for (int half_ = 0; half_ < 2; half_++) {
            int n = m0 + wm * 16 + gid + half_ * 8;
            if (n < n_nodes) {
                float2 v;
                v.x = fmaxf(acc[nt][2 * half_ + 0] + b0, 0.f);
                v.y = fmaxf(acc[nt][2 * half_ + 1] + b1, 0.f);
                *(float2*)(out + (size_t)n * DOUT + o) = v;
            }
        }
    }
}

// ---------------- launch ------------------------------------------------------
extern "C" void kernel_launch(void* const* d_in, const int* in_sizes, int n_in,
                              void* d_out, int out_size) {
    const float* x    = (const float*)d_in[0];
    const void*  ei   = d_in[1];
    const float* attr = (const float*)d_in[2];
    const float* W1   = (const float*)d_in[3];
    const float* b1   = (const float*)d_in[4];
    const float* W2   = (const float*)d_in[5];
    const float* b2   = (const float*)d_in[6];
    const float* root = (const float*)d_in[7];
    const float* bias = (const float*)d_in[8];
    float* out = (float*)d_out;

    int N = in_sizes[0] / DIN;
    int E = in_sizes[2] / BFD;
    if (N > NMAX) N = NMAX;
    if (E > EMAX) E = EMAX;

    void* degp = nullptr;
    cudaGetSymbolAddress(&degp, g_deg);
    cudaMemsetAsync(degp, 0, (size_t)N * sizeof(int));

    static int smem_set = 0;
    if (!smem_set) {
        cudaFuncSetAttribute(gemm_mma_kernel, cudaFuncAttributeMaxDynamicSharedMemorySize, GEMM_SMEM);
        smem_set = 1;
    }

    decode_count_kernel<<<264, 256>>>(ei, E);
    scan_kernel<<<1, 1024>>>(N);
    scatter_kernel<<<264, 256>>>(E);
    attr16_kernel<<<(E + 255) / 256, 256>>>(attr, E);
    w1t16_kernel<<<(DHID * 16 + 255) / 256, 256>>>(W1);
    hmma_kernel<<<(E + 127) / 128, 256>>>(b1, E);
    wt_kernel<<<dim3(NTILES, 2), dim3(32, 32)>>>(W2, b2, root);
    xh_kernel<<<(N * DIN + 255) / 256, 256>>>(x, N * DIN);
    sbuild_tc_kernel<<<N, 128>>>(N);
    gemm_mma_kernel<<<(N + MT - 1) / MT, 256, GEMM_SMEM>>>(bias, out, N);
}